// round 13
// baseline (speedup 1.0000x reference)
#include <cuda_runtime.h>
#include <cuda_fp16.h>
#include <cstdint>
#include <math.h>

#define Bb 2
#define Ss 2048
#define Dd 1024
#define NH 16
#define NKV 4
#define HD 64
#define MM (Bb*Ss)

// ---------------- scratch (__device__ globals) ------------------------------
__device__ __align__(16) __half g_xh [MM * Dd];
__device__ __align__(16) __half g_wh [1536 * Dd];
__device__ __align__(16) __half g_woh[Dd * 1024];
__device__ __align__(16) __half g_qkvh[MM * 1536];
__device__ __align__(16) __half g_qh [Bb*NH *Ss*HD];
__device__ __align__(16) __half g_kh [Bb*NKV*Ss*HD];
__device__ __align__(16) __half g_oh [MM * NH*HD];
__device__ __align__(16) float2 g_rope[Ss * 32];     // (cos, sin) table

// ---------------- warp-MMA helpers ------------------------------------------
__device__ __forceinline__ uint32_t smem_u32(const void* p) {
    uint32_t a;
    asm("{ .reg .u64 t; cvta.to.shared.u64 t, %1; cvt.u32.u64 %0, t; }" : "=r"(a) : "l"(p));
    return a;
}
__device__ __forceinline__ void mma16816(float* c, const uint32_t* a, uint32_t b0, uint32_t b1) {
    asm volatile("mma.sync.aligned.m16n8k16.row.col.f32.f16.f16.f32 "
                 "{%0,%1,%2,%3}, {%4,%5,%6,%7}, {%8,%9}, {%0,%1,%2,%3};"
                 : "+f"(c[0]), "+f"(c[1]), "+f"(c[2]), "+f"(c[3])
                 : "r"(a[0]), "r"(a[1]), "r"(a[2]), "r"(a[3]), "r"(b0), "r"(b1));
}
__device__ __forceinline__ void mma16816h(uint32_t* c, const uint32_t* a, uint32_t b0, uint32_t b1) {
    asm volatile("mma.sync.aligned.m16n8k16.row.col.f16.f16.f16.f16 "
                 "{%0,%1}, {%2,%3,%4,%5}, {%6,%7}, {%0,%1};"
                 : "+r"(c[0]), "+r"(c[1])
                 : "r"(a[0]), "r"(a[1]), "r"(a[2]), "r"(a[3]), "r"(b0), "r"(b1));
}
__device__ __forceinline__ void ldsm_x4(uint32_t* r, uint32_t a) {
    asm volatile("ldmatrix.sync.aligned.m8n8.x4.shared.b16 {%0,%1,%2,%3}, [%4];"
                 : "=r"(r[0]), "=r"(r[1]), "=r"(r[2]), "=r"(r[3]) : "r"(a));
}
__device__ __forceinline__ void ldsm_x4t(uint32_t* r, uint32_t a) {
    asm volatile("ldmatrix.sync.aligned.m8n8.x4.trans.shared.b16 {%0,%1,%2,%3}, [%4];"
                 : "=r"(r[0]), "=r"(r[1]), "=r"(r[2]), "=r"(r[3]) : "r"(a));
}
__device__ __forceinline__ uint32_t packh2(float x, float y) {
    __half2 h = __floats2half2_rn(x, y);
    return *reinterpret_cast<uint32_t*>(&h);
}
__device__ __forceinline__ void cp16(uint32_t dst, const void* src) {
    asm volatile("cp.async.cg.shared.global [%0], [%1], 16;" :: "r"(dst), "l"(src));
}
__device__ __forceinline__ __half2 u2h(uint32_t u) { return *reinterpret_cast<__half2*>(&u); }
__device__ __forceinline__ uint32_t h2u(__half2 h) { return *reinterpret_cast<uint32_t*>(&h); }
__device__ __forceinline__ float ex2a(float x) {
    float y;
    asm("ex2.approx.ftz.f32 %0, %1;" : "=f"(y) : "f"(x));
    return y;
}

// ---------------- fused fp32->fp16 conversions + rope table -----------------
__global__ void convall(const float* __restrict__ x,  const float* __restrict__ wq,
                        const float* __restrict__ wk, const float* __restrict__ wv,
                        const float* __restrict__ wo) {
    int i = blockIdx.x * blockDim.x + threadIdx.x;
    if (i >= 1703936) {
        if (i < 1703936 + Ss * 32) {
            int t = i - 1703936, s = t >> 5, j = t & 31;
            float ang = (float)s * expf(-(float)j * (9.210340371976184f / 32.f));
            float sn, cs; sincosf(ang, &sn, &cs);
            g_rope[t] = make_float2(cs, sn);
        }
        return;
    }
    const float4* s; __half2* d;
    if      (i < 1048576) {                      s = (const float4*)x  + i; d = (__half2*)g_xh            + 2 * i; }
    else if (i < 1310720) { int t = i - 1048576; s = (const float4*)wq + t; d = (__half2*)g_wh            + 2 * t; }
    else if (i < 1376256) { int t = i - 1310720; s = (const float4*)wk + t; d = (__half2*)(g_wh + 1048576) + 2 * t; }
    else if (i < 1441792) { int t = i - 1376256; s = (const float4*)wv + t; d = (__half2*)(g_wh + 1310720) + 2 * t; }
    else                  { int t = i - 1441792; s = (const float4*)wo + t; d = (__half2*)g_woh           + 2 * t; }
    float4 v = *s;
    d[0] = __floats2half2_rn(v.x, v.y);
    d[1] = __floats2half2_rn(v.z, v.w);
}

// ---------------- HMMA GEMM, 256 thr, warp 64x32, BK=64, cp.async 3-stage ---
#define AST 72
#define GEMM_SMEM 110592
template<bool HALF_OUT>
__global__ __launch_bounds__(256) void gemm_f16(const __half* __restrict__ A,
                                                const __half* __restrict__ B,
                                                void* __restrict__ Cv,
                                                int N, int K) {
    extern __shared__ __align__(16) char gsm[];
    const uint32_t gsb = smem_u32(gsm);
    const int tid = threadIdx.x, lane = tid & 31, wid = tid >> 5;
    const int wm = wid & 1, wn = wid >> 1;
    const int m0 = blockIdx.y * 128, n0 = blockIdx.x * 128;
    const int gid = lane >> 2, tig = lane & 3;
    const int rr = tid >> 3, cc8 = (tid & 7) * 8;

    float acc[4][4][4];
#pragma unroll
    for (int mi = 0; mi < 4; mi++)
#pragma unroll
        for (int ni = 0; ni < 4; ni++)
#pragma unroll
            for (int j = 0; j < 4; j++) acc[mi][ni][j] = 0.f;

    const int NKt = K >> 6;
#pragma unroll
    for (int st = 0; st < 2; st++) {
        if (st < NKt) {
            const int k0 = st << 6;
            uint32_t ab = gsb + st * 36864;
#pragma unroll
            for (int i = 0; i < 4; i++) {
                const int row = rr + i * 32;
                cp16(ab + ((row * AST + cc8) << 1),         A + (size_t)(m0 + row) * K + k0 + cc8);
                cp16(ab + 18432 + ((row * AST + cc8) << 1), B + (size_t)(n0 + row) * K + k0 + cc8);
            }
        }
        asm volatile("cp.async.commit_group;");
    }
    asm volatile("cp.async.wait_group 1;" ::: "memory");
    __syncthreads();

    int sc = 0, sp = 2;
    for (int kt = 0; kt < NKt; kt++) {
        if (kt + 2 < NKt) {
            const int k0 = (kt + 2) << 6;
            uint32_t ab = gsb + sp * 36864;
#pragma unroll
            for (int i = 0; i < 4; i++) {
                const int row = rr + i * 32;
                cp16(ab + ((row * AST + cc8) << 1),         A + (size_t)(m0 + row) * K + k0 + cc8);
                cp16(ab + 18432 + ((row * AST + cc8) << 1), B + (size_t)(n0 + row) * K + k0 + cc8);
            }
        }
        asm volatile("cp.async.commit_group;");

        const uint32_t asb = gsb + sc * 36864;
        const uint32_t bsb = asb + 18432;
#pragma unroll
        for (int ks = 0; ks < 4; ks++) {
            uint32_t af[4][4];
#pragma unroll
            for (int mi = 0; mi < 4; mi++)
                ldsm_x4(af[mi], asb + (((wm * 64 + mi * 16 + (lane & 15)) * AST
                                        + ks * 16 + (lane >> 4) * 8) << 1));
            uint32_t bfr[2][4];
#pragma unroll
            for (int ni2 = 0; ni2 < 2; ni2++)
                ldsm_x4(bfr[ni2], bsb + (((wn * 32 + ni2 * 16 + (lane & 15)) * AST
                                          + ks * 16 + (lane >> 4) * 8) << 1));
#pragma unroll
            for (int ni = 0; ni < 4; ni++) {
                const uint32_t b0 = bfr[ni >> 1][ni & 1], b1 = bfr[ni >> 1][(ni & 1) + 2];
#pragma unroll
                for (int mi = 0; mi < 4; mi++) mma16816(acc[mi][ni], af[mi], b0, b1);
            }
        }
        asm volatile("cp.async.wait_group 1;" ::: "memory");
        __syncthreads();
        sc = (sc == 2) ? 0 : sc + 1;
        sp = (sp == 2) ? 0 : sp + 1;
    }

#pragma unroll
    for (int mi = 0; mi < 4; mi++)
#pragma unroll
        for (int ni = 0; ni < 4; ni++) {
            const int row = m0 + wm * 64 + mi * 16 + gid;
            const int col = n0 + wn * 32 + ni * 8 + tig * 2;
            if (HALF_OUT) {
                __half* C = (__half*)Cv;
                *(__half2*)&C[(size_t)row * N + col]       = __floats2half2_rn(acc[mi][ni][0], acc[mi][ni][1]);
                *(__half2*)&C[(size_t)(row + 8) * N + col] = __floats2half2_rn(acc[mi][ni][2], acc[mi][ni][3]);
            } else {
                float* C = (float*)Cv;
                *(float2*)&C[(size_t)row * N + col]       = make_float2(acc[mi][ni][0], acc[mi][ni][1]);
                *(float2*)&C[(size_t)(row + 8) * N + col] = make_float2(acc[mi][ni][2], acc[mi][ni][3]);
            }
        }
}

// ---------------- fused RoPE (q/k only; V read in-place by flash) ------------
#define QSCALE 0.1803368801111204f
__global__ void prep(const __half* __restrict__ qkv) {
    int idx = blockIdx.x * blockDim.x + threadIdx.x;
    if (idx < MM * NH * 32) {
        int j = idx & 31, hh = (idx >> 5) & 15, row = idx >> 9;
        int s = row & (Ss - 1), b = row >> 11;
        float2 r = g_rope[(s << 5) | j];
        const __half* p = qkv + (size_t)row * 1536 + hh * 64;
        float x1 = __half2float(p[j]), x2 = __half2float(p[j + 32]);
        __half* o = g_qh + ((size_t)(b * NH + hh) * Ss + s) * HD;
        o[j]      = __float2half((x1 * r.x - x2 * r.y) * QSCALE);
        o[j + 32] = __float2half((x2 * r.x + x1 * r.y) * QSCALE);
    } else if (idx < MM * NH * 32 + MM * NKV * 32) {
        int t = idx - MM * NH * 32;
        int j = t & 31, hh = (t >> 5) & 3, row = t >> 7;
        int s = row & (Ss - 1), b = row >> 11;
        float2 r = g_rope[(s << 5) | j];
        const __half* p = qkv + (size_t)row * 1536 + 1024 + hh * 64;
        float x1 = __half2float(p[j]), x2 = __half2float(p[j + 32]);
        __half* o = g_kh + ((size_t)(b * NKV + hh) * Ss + s) * HD;
        o[j]      = __float2half(x1 * r.x - x2 * r.y);
        o[j + 32] = __float2half(x2 * r.x + x1 * r.y);
    }
}

// ---------------- flash attention: Q smem aliased with K-buf1, 5 CTAs/SM ----
// smem layout: K0 @0 | V0 @9216 | K1(=Q) @18432 | V1 @27648 -> 36864 B total.
#define FST 72
#define FLASH_SMEM 36864
__global__ __launch_bounds__(128, 5) void flash_f16() {
    extern __shared__ __align__(16) char sm[];
    const uint32_t sb = smem_u32(sm);
    const uint32_t qsb = sb + 18432;                 // aliased with K buffer 1
    __half* Qs = (__half*)(sm + 18432);

    const int tid = threadIdx.x, lane = tid & 31, w = tid >> 5;
    const int qt = (gridDim.x - 1) - blockIdx.x;     // heavy blocks first
    const int h = blockIdx.y, b = blockIdx.z;
    const int qm0 = qt * 64, kvh = h >> 2, qw0 = w * 16;
    const int gid = lane >> 2, tig = lane & 3;

    const __half* kb = g_kh + (size_t)(b * NKV + kvh) * Ss * HD;
    // V read directly from qkvh: row (b*Ss+s), cols 1280 + kvh*64 .. +64
    const __half* vb = g_qkvh + (size_t)b * Ss * 1536 + 1280 + kvh * 64;
    const int cr = tid >> 3, cc = (tid & 7) * 8;

    // prologue: tile 0 -> buf 0 (K@0, V@9216)
#pragma unroll
    for (int i = 0; i < 4; i++) {
        cp16(sb + (((cr + i * 16) * FST + cc) << 1),        kb + (size_t)(cr + i * 16) * HD + cc);
        cp16(sb + 9216 + (((cr + i * 16) * FST + cc) << 1), vb + (size_t)(cr + i * 16) * 1536 + cc);
    }
    asm volatile("cp.async.commit_group;");

    const __half* qb = g_qh + ((size_t)(b * NH + h) * Ss + qm0) * HD;
#pragma unroll
    for (int i = 0; i < 4; i++) {
        int u = tid + i * 128, r = u >> 3, c = u & 7;
        *(uint4*)&Qs[r * FST + c * 8] = *(const uint4*)(qb + (size_t)r * HD + c * 8);
    }
    asm volatile("cp.async.wait_group 0;" ::: "memory");
    __syncthreads();

    uint32_t aQ[4][4];
#pragma unroll
    for (int ks = 0; ks < 4; ks++)
        ldsm_x4(aQ[ks], qsb + (((qw0 + (lane & 15)) * FST + ks * 16 + (lane >> 4) * 8) << 1));
    __syncthreads();   // all warps done reading Q before buf1 (aliased) is filled

    float oacc[8][4];
#pragma unroll
    for (int ni = 0; ni < 8; ni++)
#pragma unroll
        for (int j = 0; j < 4; j++) oacc[ni][j] = 0.f;
    float m0_ = -1e30f, m1_ = -1e30f, l0_ = 0.f, l1_ = 0.f;
    const int row0 = qm0 + qw0 + gid, row1 = row0 + 8;

    const int ntiles = qt + 1;
    int buf = 0;
    for (int t = 0; t < ntiles; t++) {
        const int n0 = t * 64;
        if (t + 1 < ntiles) {
            const int nn = n0 + 64;
            const uint32_t kd = sb + (buf ^ 1) * 18432, vd = kd + 9216;
#pragma unroll
            for (int i = 0; i < 4; i++) {
                cp16(kd + (((cr + i * 16) * FST + cc) << 1), kb + (size_t)(nn + cr + i * 16) * HD + cc);
                cp16(vd + (((cr + i * 16) * FST + cc) << 1), vb + (size_t)(nn + cr + i * 16) * 1536 + cc);
            }
        }
        asm volatile("cp.async.commit_group;");

        {
            const uint32_t ksb = sb + buf * 18432, vsb = ksb + 9216;

            uint32_t sh[8][2];
#pragma unroll
            for (int ni = 0; ni < 8; ni++) { sh[ni][0] = 0u; sh[ni][1] = 0u; }
#pragma unroll
            for (int ks = 0; ks < 4; ks++)
#pragma unroll
                for (int ni2 = 0; ni2 < 4; ni2++) {
                    uint32_t kr[4];
                    ldsm_x4(kr, ksb + (((ni2 * 16 + (lane & 15)) * FST + ks * 16 + (lane >> 4) * 8) << 1));
                    mma16816h(sh[ni2 * 2],     aQ[ks], kr[0], kr[2]);
                    mma16816h(sh[ni2 * 2 + 1], aQ[ks], kr[1], kr[3]);
                }

            float sacc[8][4];
#pragma unroll
            for (int ni = 0; ni < 8; ni++) {
                float2 lo = __half22float2(u2h(sh[ni][0]));
                float2 hi = __half22float2(u2h(sh[ni][1]));
                sacc[ni][0] = lo.x; sacc[ni][1] = lo.y; sacc[ni][2] = hi.x; sacc[ni][3] = hi.y;
            }
            if (n0 + 63 > row0) {
#pragma unroll
                for (int ni = 0; ni < 8; ni++) {
                    const int col = n0 + ni * 8 + tig * 2;
                    if (col     > row0) sacc[ni][0] = -1e30f;
                    if (col + 1 > row0) sacc[ni][1] = -1e30f;
                    if (col     > row1) sacc[ni][2] = -1e30f;
                    if (col + 1 > row1) sacc[ni][3] = -1e30f;
                }
            }

            float mx0 = -1e30f, mx1 = -1e30f;
#pragma unroll
            for (int ni = 0; ni < 8; ni++) {
                mx0 = fmaxf(mx0, fmaxf(sacc[ni][0], sacc[ni][1]));
                mx1 = fmaxf(mx1, fmaxf(sacc[ni][2], sacc[ni][3]));
            }
            __half2 mp = __floats2half2_rn(mx0, mx1);
            {
                uint32_t mu = h2u(mp);
                uint32_t o1 = __shfl_xor_sync(0xffffffffu, mu, 1);
                mp = __hmax2(mp, u2h(o1));
                mu = h2u(mp);
                uint32_t o2 = __shfl_xor_sync(0xffffffffu, mu, 2);
                mp = __hmax2(mp, u2h(o2));
            }
            float2 mf = __half22float2(mp);
            const float mn0 = fmaxf(m0_, mf.x), mn1 = fmaxf(m1_, mf.y);
            const float al0 = ex2a(m0_ - mn0), al1 = ex2a(m1_ - mn1);

            float s0 = 0.f, s1 = 0.f;
#pragma unroll
            for (int ni = 0; ni < 8; ni++) {
                sacc[ni][0] = ex2a(sacc[ni][0] - mn0);
                sacc[ni][1] = ex2a(sacc[ni][1] - mn0);
                sacc[ni][2] = ex2a(sacc[ni][2] - mn1);
                sacc[ni][3] = ex2a(sacc[ni][3] - mn1);
                s0 += sacc[ni][0] + sacc[ni][1];
                s1 += sacc[ni][2] + sacc[ni][3];
            }
            l0_ = l0_ * al0 + s0;
            l1_ = l1_ * al1 + s1;
            m0_ = mn0; m1_ = mn1;

            uint32_t aP[4][4];
#pragma unroll
            for (int ks = 0; ks < 4; ks++) {
                aP[ks][0] = packh2(sacc[2 * ks][0],     sacc[2 * ks][1]);
                aP[ks][1] = packh2(sacc[2 * ks][2],     sacc[2 * ks][3]);
                aP[ks][2] = packh2(sacc[2 * ks + 1][0], sacc[2 * ks + 1][1]);
                aP[ks][3] = packh2(sacc[2 * ks + 1][2], sacc[2 * ks + 1][3]);
            }
            if (!__all_sync(0xffffffffu, (al0 == 1.f) && (al1 == 1.f))) {
#pragma unroll
                for (int ni = 0; ni < 8; ni++) {
                    oacc[ni][0] *= al0; oacc[ni][1] *= al0;
                    oacc[ni][2] *= al1; oacc[ni][3] *= al1;
                }
            }
#pragma unroll
            for (int ks = 0; ks < 4; ks++)
#pragma unroll
                for (int ni2 = 0; ni2 < 4; ni2++) {
                    uint32_t vr[4];
                    ldsm_x4t(vr, vsb + (((ks * 16 + ((lane >> 3) & 1) * 8 + (lane & 7)) * FST
                                         + ni2 * 16 + (lane >> 4) * 8) << 1));
                    mma16816(oacc[ni2 * 2],     aP[ks], vr[0], vr[1]);
                    mma16816(oacc[ni2 * 2 + 1], aP[ks], vr[2], vr[3]);
                }
        }

        asm volatile("cp.async.wait_group 0;" ::: "memory");
        __syncthreads();
        buf ^= 1;
    }

    l0_ += __shfl_xor_sync(0xffffffffu, l0_, 1);
    l0_ += __shfl_xor_sync(0xffffffffu, l0_, 2);
    l1_ += __shfl_xor_sync(0xffffffffu, l1_, 1);
    l1_ += __shfl_xor_sync(0xffffffffu, l1_, 2);
    const float inv0 = 1.f / l0_, inv1 = 1.f / l1_;
    __half* ob = g_oh + (size_t)(b * Ss + qm0 + qw0) * (NH * HD) + h * HD;
#pragma unroll
    for (int ni = 0; ni < 8; ni++) {
        const int col = ni * 8 + tig * 2;
        __half2 o0 = __floats2half2_rn(oacc[ni][0] * inv0, oacc[ni][1] * inv0);
        __half2 o1 = __floats2half2_rn(oacc[ni][2] * inv1, oacc[ni][3] * inv1);
        *(__half2*)&ob[(size_t)gid * (NH * HD) + col]       = o0;
        *(__half2*)&ob[(size_t)(gid + 8) * (NH * HD) + col] = o1;
    }
}

// ---------------------------------------------------------------------------
extern "C" void kernel_launch(void* const* d_in, const int* in_sizes, int n_in,
                              void* d_out, int out_size) {
    const float* x  = (const float*)d_in[0];
    const float* Wq = (const float*)d_in[1];
    const float* Wk = (const float*)d_in[2];
    const float* Wv = (const float*)d_in[3];
    const float* Wo = (const float*)d_in[4];
    float* out = (float*)d_out;

    __half *xh, *wh, *woh, *oh, *qkvh;
    cudaGetSymbolAddress((void**)&xh,   g_xh);
    cudaGetSymbolAddress((void**)&wh,   g_wh);
    cudaGetSymbolAddress((void**)&woh,  g_woh);
    cudaGetSymbolAddress((void**)&oh,   g_oh);
    cudaGetSymbolAddress((void**)&qkvh, g_qkvh);

    cudaFuncSetAttribute(flash_f16, cudaFuncAttributeMaxDynamicSharedMemorySize, FLASH_SMEM);
    cudaFuncSetAttribute(gemm_f16<true>,  cudaFuncAttributeMaxDynamicSharedMemorySize, GEMM_SMEM);
    cudaFuncSetAttribute(gemm_f16<false>, cudaFuncAttributeMaxDynamicSharedMemorySize, GEMM_SMEM);

    convall<<<(1703936 + Ss * 32 + 255) / 256, 256>>>(x, Wq, Wk, Wv, Wo);
    gemm_f16<true><<<dim3(12, 32), 256, GEMM_SMEM>>>(xh, wh, qkvh, 1536, 1024);
    prep<<<(MM * NH * 32 + MM * NKV * 32 + 255) / 256, 256>>>(qkvh);
    flash_f16<<<dim3(32, NH, Bb), 128, FLASH_SMEM>>>();
    gemm_f16<false><<<dim3(8, 32), 256, GEMM_SMEM>>>(oh, woh, out, 1024, 1024);
}

// round 14
// speedup vs baseline: 1.0022x; 1.0022x over previous
#include <cuda_runtime.h>
#include <cuda_fp16.h>
#include <cstdint>
#include <math.h>

#define Bb 2
#define Ss 2048
#define Dd 1024
#define NH 16
#define NKV 4
#define HD 64
#define MM (Bb*Ss)

// ---------------- scratch (__device__ globals) ------------------------------
__device__ __align__(16) __half g_xh [MM * Dd];
__device__ __align__(16) __half g_wh [1536 * Dd];
__device__ __align__(16) __half g_woh[Dd * 1024];
__device__ __align__(16) __half g_qkvh[MM * 1536];
__device__ __align__(16) __half g_qh [Bb*NH *Ss*HD];
__device__ __align__(16) __half g_kh [Bb*NKV*Ss*HD];
__device__ __align__(16) __half g_vh [Bb*NKV*Ss*HD];
__device__ __align__(16) __half g_oh [MM * NH*HD];
__device__ __align__(16) float2 g_rope[Ss * 32];     // (cos, sin) table

// ---------------- warp-MMA helpers ------------------------------------------
__device__ __forceinline__ uint32_t smem_u32(const void* p) {
    uint32_t a;
    asm("{ .reg .u64 t; cvta.to.shared.u64 t, %1; cvt.u32.u64 %0, t; }" : "=r"(a) : "l"(p));
    return a;
}
__device__ __forceinline__ void mma16816(float* c, const uint32_t* a, uint32_t b0, uint32_t b1) {
    asm volatile("mma.sync.aligned.m16n8k16.row.col.f32.f16.f16.f32 "
                 "{%0,%1,%2,%3}, {%4,%5,%6,%7}, {%8,%9}, {%0,%1,%2,%3};"
                 : "+f"(c[0]), "+f"(c[1]), "+f"(c[2]), "+f"(c[3])
                 : "r"(a[0]), "r"(a[1]), "r"(a[2]), "r"(a[3]), "r"(b0), "r"(b1));
}
__device__ __forceinline__ void mma16816h(uint32_t* c, const uint32_t* a, uint32_t b0, uint32_t b1) {
    asm volatile("mma.sync.aligned.m16n8k16.row.col.f16.f16.f16.f16 "
                 "{%0,%1}, {%2,%3,%4,%5}, {%6,%7}, {%0,%1};"
                 : "+r"(c[0]), "+r"(c[1])
                 : "r"(a[0]), "r"(a[1]), "r"(a[2]), "r"(a[3]), "r"(b0), "r"(b1));
}
__device__ __forceinline__ void ldsm_x4(uint32_t* r, uint32_t a) {
    asm volatile("ldmatrix.sync.aligned.m8n8.x4.shared.b16 {%0,%1,%2,%3}, [%4];"
                 : "=r"(r[0]), "=r"(r[1]), "=r"(r[2]), "=r"(r[3]) : "r"(a));
}
__device__ __forceinline__ void ldsm_x4t(uint32_t* r, uint32_t a) {
    asm volatile("ldmatrix.sync.aligned.m8n8.x4.trans.shared.b16 {%0,%1,%2,%3}, [%4];"
                 : "=r"(r[0]), "=r"(r[1]), "=r"(r[2]), "=r"(r[3]) : "r"(a));
}
__device__ __forceinline__ uint32_t packh2(float x, float y) {
    __half2 h = __floats2half2_rn(x, y);
    return *reinterpret_cast<uint32_t*>(&h);
}
__device__ __forceinline__ void cp16(uint32_t dst, const void* src) {
    asm volatile("cp.async.cg.shared.global [%0], [%1], 16;" :: "r"(dst), "l"(src));
}
__device__ __forceinline__ __half2 u2h(uint32_t u) { return *reinterpret_cast<__half2*>(&u); }
__device__ __forceinline__ uint32_t h2u(__half2 h) { return *reinterpret_cast<uint32_t*>(&h); }
__device__ __forceinline__ float ex2a(float x) {
    float y;
    asm("ex2.approx.ftz.f32 %0, %1;" : "=f"(y) : "f"(x));
    return y;
}

// ---------------- fused fp32->fp16 conversions + rope table -----------------
__global__ void convall(const float* __restrict__ x,  const float* __restrict__ wq,
                        const float* __restrict__ wk, const float* __restrict__ wv,
                        const float* __restrict__ wo) {
    int i = blockIdx.x * blockDim.x + threadIdx.x;
    if (i >= 1703936) {
        if (i < 1703936 + Ss * 32) {
            int t = i - 1703936, s = t >> 5, j = t & 31;
            float ang = (float)s * expf(-(float)j * (9.210340371976184f / 32.f));
            float sn, cs; sincosf(ang, &sn, &cs);
            g_rope[t] = make_float2(cs, sn);
        }
        return;
    }
    const float4* s; __half2* d;
    if      (i < 1048576) {                      s = (const float4*)x  + i; d = (__half2*)g_xh            + 2 * i; }
    else if (i < 1310720) { int t = i - 1048576; s = (const float4*)wq + t; d = (__half2*)g_wh            + 2 * t; }
    else if (i < 1376256) { int t = i - 1310720; s = (const float4*)wk + t; d = (__half2*)(g_wh + 1048576) + 2 * t; }
    else if (i < 1441792) { int t = i - 1376256; s = (const float4*)wv + t; d = (__half2*)(g_wh + 1310720) + 2 * t; }
    else                  { int t = i - 1441792; s = (const float4*)wo + t; d = (__half2*)g_woh           + 2 * t; }
    float4 v = *s;
    d[0] = __floats2half2_rn(v.x, v.y);
    d[1] = __floats2half2_rn(v.z, v.w);
}

// ---------------- HMMA GEMM, 256 thr, warp 64x32, BK=64, cp.async 3-stage ---
#define AST 72
#define GEMM_SMEM 110592
template<bool HALF_OUT>
__global__ __launch_bounds__(256) void gemm_f16(const __half* __restrict__ A,
                                                const __half* __restrict__ B,
                                                void* __restrict__ Cv,
                                                int N, int K) {
    extern __shared__ __align__(16) char gsm[];
    const uint32_t gsb = smem_u32(gsm);
    const int tid = threadIdx.x, lane = tid & 31, wid = tid >> 5;
    const int wm = wid & 1, wn = wid >> 1;
    const int m0 = blockIdx.y * 128, n0 = blockIdx.x * 128;
    const int gid = lane >> 2, tig = lane & 3;
    const int rr = tid >> 3, cc8 = (tid & 7) * 8;

    float acc[4][4][4];
#pragma unroll
    for (int mi = 0; mi < 4; mi++)
#pragma unroll
        for (int ni = 0; ni < 4; ni++)
#pragma unroll
            for (int j = 0; j < 4; j++) acc[mi][ni][j] = 0.f;

    const int NKt = K >> 6;
#pragma unroll
    for (int st = 0; st < 2; st++) {
        if (st < NKt) {
            const int k0 = st << 6;
            uint32_t ab = gsb + st * 36864;
#pragma unroll
            for (int i = 0; i < 4; i++) {
                const int row = rr + i * 32;
                cp16(ab + ((row * AST + cc8) << 1),         A + (size_t)(m0 + row) * K + k0 + cc8);
                cp16(ab + 18432 + ((row * AST + cc8) << 1), B + (size_t)(n0 + row) * K + k0 + cc8);
            }
        }
        asm volatile("cp.async.commit_group;");
    }
    asm volatile("cp.async.wait_group 1;" ::: "memory");
    __syncthreads();

    int sc = 0, sp = 2;
    for (int kt = 0; kt < NKt; kt++) {
        if (kt + 2 < NKt) {
            const int k0 = (kt + 2) << 6;
            uint32_t ab = gsb + sp * 36864;
#pragma unroll
            for (int i = 0; i < 4; i++) {
                const int row = rr + i * 32;
                cp16(ab + ((row * AST + cc8) << 1),         A + (size_t)(m0 + row) * K + k0 + cc8);
                cp16(ab + 18432 + ((row * AST + cc8) << 1), B + (size_t)(n0 + row) * K + k0 + cc8);
            }
        }
        asm volatile("cp.async.commit_group;");

        const uint32_t asb = gsb + sc * 36864;
        const uint32_t bsb = asb + 18432;
#pragma unroll
        for (int ks = 0; ks < 4; ks++) {
            uint32_t af[4][4];
#pragma unroll
            for (int mi = 0; mi < 4; mi++)
                ldsm_x4(af[mi], asb + (((wm * 64 + mi * 16 + (lane & 15)) * AST
                                        + ks * 16 + (lane >> 4) * 8) << 1));
            uint32_t bfr[2][4];
#pragma unroll
            for (int ni2 = 0; ni2 < 2; ni2++)
                ldsm_x4(bfr[ni2], bsb + (((wn * 32 + ni2 * 16 + (lane & 15)) * AST
                                          + ks * 16 + (lane >> 4) * 8) << 1));
#pragma unroll
            for (int ni = 0; ni < 4; ni++) {
                const uint32_t b0 = bfr[ni >> 1][ni & 1], b1 = bfr[ni >> 1][(ni & 1) + 2];
#pragma unroll
                for (int mi = 0; mi < 4; mi++) mma16816(acc[mi][ni], af[mi], b0, b1);
            }
        }
        asm volatile("cp.async.wait_group 1;" ::: "memory");
        __syncthreads();
        sc = (sc == 2) ? 0 : sc + 1;
        sp = (sp == 2) ? 0 : sp + 1;
    }

#pragma unroll
    for (int mi = 0; mi < 4; mi++)
#pragma unroll
        for (int ni = 0; ni < 4; ni++) {
            const int row = m0 + wm * 64 + mi * 16 + gid;
            const int col = n0 + wn * 32 + ni * 8 + tig * 2;
            if (HALF_OUT) {
                __half* C = (__half*)Cv;
                *(__half2*)&C[(size_t)row * N + col]       = __floats2half2_rn(acc[mi][ni][0], acc[mi][ni][1]);
                *(__half2*)&C[(size_t)(row + 8) * N + col] = __floats2half2_rn(acc[mi][ni][2], acc[mi][ni][3]);
            } else {
                float* C = (float*)Cv;
                *(float2*)&C[(size_t)row * N + col]       = make_float2(acc[mi][ni][0], acc[mi][ni][1]);
                *(float2*)&C[(size_t)(row + 8) * N + col] = make_float2(acc[mi][ni][2], acc[mi][ni][3]);
            }
        }
}

// ---------------- fused RoPE + V layout (fp16 qkv input) ---------------------
#define QSCALE 0.1803368801111204f
__global__ void prep(const __half* __restrict__ qkv) {
    int idx = blockIdx.x * blockDim.x + threadIdx.x;
    if (idx < MM * NH * 32) {
        int j = idx & 31, hh = (idx >> 5) & 15, row = idx >> 9;
        int s = row & (Ss - 1), b = row >> 11;
        float2 r = g_rope[(s << 5) | j];
        const __half* p = qkv + (size_t)row * 1536 + hh * 64;
        float x1 = __half2float(p[j]), x2 = __half2float(p[j + 32]);
        __half* o = g_qh + ((size_t)(b * NH + hh) * Ss + s) * HD;
        o[j]      = __float2half((x1 * r.x - x2 * r.y) * QSCALE);
        o[j + 32] = __float2half((x2 * r.x + x1 * r.y) * QSCALE);
    } else if (idx < MM * NH * 32 + MM * NKV * 32) {
        int t = idx - MM * NH * 32;
        int j = t & 31, hh = (t >> 5) & 3, row = t >> 7;
        int s = row & (Ss - 1), b = row >> 11;
        float2 r = g_rope[(s << 5) | j];
        const __half* p = qkv + (size_t)row * 1536 + 1024 + hh * 64;
        float x1 = __half2float(p[j]), x2 = __half2float(p[j + 32]);
        __half* o = g_kh + ((size_t)(b * NKV + hh) * Ss + s) * HD;
        o[j]      = __float2half(x1 * r.x - x2 * r.y);
        o[j + 32] = __float2half(x2 * r.x + x1 * r.y);
    } else if (idx < MM * NH * 32 + MM * NKV * 32 + MM * NKV * 8) {
        int t = idx - (MM * NH * 32 + MM * NKV * 32);
        int d8 = t & 7, hh = (t >> 3) & 3, row = t >> 5;
        int s = row & (Ss - 1), b = row >> 11;
        uint4 v = *(const uint4*)(qkv + (size_t)row * 1536 + 1280 + hh * 64 + d8 * 8);
        *(uint4*)(g_vh + ((size_t)(b * NKV + hh) * Ss + s) * HD + d8 * 8) = v;
    }
}

// ---------------- flash attention: Q aliased with K-buf1, dense V, 5 CTA ----
// smem layout: K0 @0 | V0 @9216 | K1(=Q) @18432 | V1 @27648 -> 36864 B total.
#define FST 72
#define FLASH_SMEM 36864
__global__ __launch_bounds__(128, 5) void flash_f16() {
    extern __shared__ __align__(16) char sm[];
    const uint32_t sb = smem_u32(sm);
    const uint32_t qsb = sb + 18432;                 // aliased with K buffer 1
    __half* Qs = (__half*)(sm + 18432);

    const int tid = threadIdx.x, lane = tid & 31, w = tid >> 5;
    const int qt = (gridDim.x - 1) - blockIdx.x;     // heavy blocks first
    const int h = blockIdx.y, b = blockIdx.z;
    const int qm0 = qt * 64, kvh = h >> 2, qw0 = w * 16;
    const int gid = lane >> 2, tig = lane & 3;

    const __half* kb = g_kh + (size_t)(b * NKV + kvh) * Ss * HD;
    const __half* vb = g_vh + (size_t)(b * NKV + kvh) * Ss * HD;
    const int cr = tid >> 3, cc = (tid & 7) * 8;

    // prologue: tile 0 -> buf 0 (K@0, V@9216)
#pragma unroll
    for (int i = 0; i < 4; i++) {
        cp16(sb + (((cr + i * 16) * FST + cc) << 1),        kb + (size_t)(cr + i * 16) * HD + cc);
        cp16(sb + 9216 + (((cr + i * 16) * FST + cc) << 1), vb + (size_t)(cr + i * 16) * HD + cc);
    }
    asm volatile("cp.async.commit_group;");

    const __half* qb = g_qh + ((size_t)(b * NH + h) * Ss + qm0) * HD;
#pragma unroll
    for (int i = 0; i < 4; i++) {
        int u = tid + i * 128, r = u >> 3, c = u & 7;
        *(uint4*)&Qs[r * FST + c * 8] = *(const uint4*)(qb + (size_t)r * HD + c * 8);
    }
    asm volatile("cp.async.wait_group 0;" ::: "memory");
    __syncthreads();

    uint32_t aQ[4][4];
#pragma unroll
    for (int ks = 0; ks < 4; ks++)
        ldsm_x4(aQ[ks], qsb + (((qw0 + (lane & 15)) * FST + ks * 16 + (lane >> 4) * 8) << 1));
    __syncthreads();   // all warps done reading Q before buf1 (aliased) is filled

    float oacc[8][4];
#pragma unroll
    for (int ni = 0; ni < 8; ni++)
#pragma unroll
        for (int j = 0; j < 4; j++) oacc[ni][j] = 0.f;
    float m0_ = -1e30f, m1_ = -1e30f, l0_ = 0.f, l1_ = 0.f;
    const int row0 = qm0 + qw0 + gid, row1 = row0 + 8;

    const int ntiles = qt + 1;
    int buf = 0;
    for (int t = 0; t < ntiles; t++) {
        const int n0 = t * 64;
        if (t + 1 < ntiles) {
            const int nn = n0 + 64;
            const uint32_t kd = sb + (buf ^ 1) * 18432, vd = kd + 9216;
#pragma unroll
            for (int i = 0; i < 4; i++) {
                cp16(kd + (((cr + i * 16) * FST + cc) << 1), kb + (size_t)(nn + cr + i * 16) * HD + cc);
                cp16(vd + (((cr + i * 16) * FST + cc) << 1), vb + (size_t)(nn + cr + i * 16) * HD + cc);
            }
        }
        asm volatile("cp.async.commit_group;");

        {
            const uint32_t ksb = sb + buf * 18432, vsb = ksb + 9216;

            uint32_t sh[8][2];
#pragma unroll
            for (int ni = 0; ni < 8; ni++) { sh[ni][0] = 0u; sh[ni][1] = 0u; }
#pragma unroll
            for (int ks = 0; ks < 4; ks++)
#pragma unroll
                for (int ni2 = 0; ni2 < 4; ni2++) {
                    uint32_t kr[4];
                    ldsm_x4(kr, ksb + (((ni2 * 16 + (lane & 15)) * FST + ks * 16 + (lane >> 4) * 8) << 1));
                    mma16816h(sh[ni2 * 2],     aQ[ks], kr[0], kr[2]);
                    mma16816h(sh[ni2 * 2 + 1], aQ[ks], kr[1], kr[3]);
                }

            float sacc[8][4];
#pragma unroll
            for (int ni = 0; ni < 8; ni++) {
                float2 lo = __half22float2(u2h(sh[ni][0]));
                float2 hi = __half22float2(u2h(sh[ni][1]));
                sacc[ni][0] = lo.x; sacc[ni][1] = lo.y; sacc[ni][2] = hi.x; sacc[ni][3] = hi.y;
            }
            if (n0 + 63 > row0) {
#pragma unroll
                for (int ni = 0; ni < 8; ni++) {
                    const int col = n0 + ni * 8 + tig * 2;
                    if (col     > row0) sacc[ni][0] = -1e30f;
                    if (col + 1 > row0) sacc[ni][1] = -1e30f;
                    if (col     > row1) sacc[ni][2] = -1e30f;
                    if (col + 1 > row1) sacc[ni][3] = -1e30f;
                }
            }

            float mx0 = -1e30f, mx1 = -1e30f;
#pragma unroll
            for (int ni = 0; ni < 8; ni++) {
                mx0 = fmaxf(mx0, fmaxf(sacc[ni][0], sacc[ni][1]));
                mx1 = fmaxf(mx1, fmaxf(sacc[ni][2], sacc[ni][3]));
            }
            __half2 mp = __floats2half2_rn(mx0, mx1);
            {
                uint32_t mu = h2u(mp);
                uint32_t o1 = __shfl_xor_sync(0xffffffffu, mu, 1);
                mp = __hmax2(mp, u2h(o1));
                mu = h2u(mp);
                uint32_t o2 = __shfl_xor_sync(0xffffffffu, mu, 2);
                mp = __hmax2(mp, u2h(o2));
            }
            float2 mf = __half22float2(mp);
            const float mn0 = fmaxf(m0_, mf.x), mn1 = fmaxf(m1_, mf.y);
            const float al0 = ex2a(m0_ - mn0), al1 = ex2a(m1_ - mn1);

            float s0 = 0.f, s1 = 0.f;
#pragma unroll
            for (int ni = 0; ni < 8; ni++) {
                sacc[ni][0] = ex2a(sacc[ni][0] - mn0);
                sacc[ni][1] = ex2a(sacc[ni][1] - mn0);
                sacc[ni][2] = ex2a(sacc[ni][2] - mn1);
                sacc[ni][3] = ex2a(sacc[ni][3] - mn1);
                s0 += sacc[ni][0] + sacc[ni][1];
                s1 += sacc[ni][2] + sacc[ni][3];
            }
            l0_ = l0_ * al0 + s0;
            l1_ = l1_ * al1 + s1;
            m0_ = mn0; m1_ = mn1;

            uint32_t aP[4][4];
#pragma unroll
            for (int ks = 0; ks < 4; ks++) {
                aP[ks][0] = packh2(sacc[2 * ks][0],     sacc[2 * ks][1]);
                aP[ks][1] = packh2(sacc[2 * ks][2],     sacc[2 * ks][3]);
                aP[ks][2] = packh2(sacc[2 * ks + 1][0], sacc[2 * ks + 1][1]);
                aP[ks][3] = packh2(sacc[2 * ks + 1][2], sacc[2 * ks + 1][3]);
            }
            if (!__all_sync(0xffffffffu, (al0 == 1.f) && (al1 == 1.f))) {
#pragma unroll
                for (int ni = 0; ni < 8; ni++) {
                    oacc[ni][0] *= al0; oacc[ni][1] *= al0;
                    oacc[ni][2] *= al1; oacc[ni][3] *= al1;
                }
            }
#pragma unroll
            for (int ks = 0; ks < 4; ks++)
#pragma unroll
                for (int ni2 = 0; ni2 < 4; ni2++) {
                    uint32_t vr[4];
                    ldsm_x4t(vr, vsb + (((ks * 16 + ((lane >> 3) & 1) * 8 + (lane & 7)) * FST
                                         + ni2 * 16 + (lane >> 4) * 8) << 1));
                    mma16816(oacc[ni2 * 2],     aP[ks], vr[0], vr[1]);
                    mma16816(oacc[ni2 * 2 + 1], aP[ks], vr[2], vr[3]);
                }
        }

        asm volatile("cp.async.wait_group 0;" ::: "memory");
        __syncthreads();
        buf ^= 1;
    }

    l0_ += __shfl_xor_sync(0xffffffffu, l0_, 1);
    l0_ += __shfl_xor_sync(0xffffffffu, l0_, 2);
    l1_ += __shfl_xor_sync(0xffffffffu, l1_, 1);
    l1_ += __shfl_xor_sync(0xffffffffu, l1_, 2);
    const float inv0 = 1.f / l0_, inv1 = 1.f / l1_;
    __half* ob = g_oh + (size_t)(b * Ss + qm0 + qw0) * (NH * HD) + h * HD;
#pragma unroll
    for (int ni = 0; ni < 8; ni++) {
        const int col = ni * 8 + tig * 2;
        __half2 o0 = __floats2half2_rn(oacc[ni][0] * inv0, oacc[ni][1] * inv0);
        __half2 o1 = __floats2half2_rn(oacc[ni][2] * inv1, oacc[ni][3] * inv1);
        *(__half2*)&ob[(size_t)gid * (NH * HD) + col]       = o0;
        *(__half2*)&ob[(size_t)(gid + 8) * (NH * HD) + col] = o1;
    }
}

// ---------------------------------------------------------------------------
extern "C" void kernel_launch(void* const* d_in, const int* in_sizes, int n_in,
                              void* d_out, int out_size) {
    const float* x  = (const float*)d_in[0];
    const float* Wq = (const float*)d_in[1];
    const float* Wk = (const float*)d_in[2];
    const float* Wv = (const float*)d_in[3];
    const float* Wo = (const float*)d_in[4];
    float* out = (float*)d_out;

    __half *xh, *wh, *woh, *oh, *qkvh;
    cudaGetSymbolAddress((void**)&xh,   g_xh);
    cudaGetSymbolAddress((void**)&wh,   g_wh);
    cudaGetSymbolAddress((void**)&woh,  g_woh);
    cudaGetSymbolAddress((void**)&oh,   g_oh);
    cudaGetSymbolAddress((void**)&qkvh, g_qkvh);

    cudaFuncSetAttribute(flash_f16, cudaFuncAttributeMaxDynamicSharedMemorySize, FLASH_SMEM);
    cudaFuncSetAttribute(gemm_f16<true>,  cudaFuncAttributeMaxDynamicSharedMemorySize, GEMM_SMEM);
    cudaFuncSetAttribute(gemm_f16<false>, cudaFuncAttributeMaxDynamicSharedMemorySize, GEMM_SMEM);

    convall<<<(1703936 + Ss * 32 + 255) / 256, 256>>>(x, Wq, Wk, Wv, Wo);
    gemm_f16<true><<<dim3(12, 32), 256, GEMM_SMEM>>>(xh, wh, qkvh, 1536, 1024);
    prep<<<(MM * NH * 32 + MM * NKV * 32 + MM * NKV * 8 + 255) / 256, 256>>>(qkvh);
    flash_f16<<<dim3(32, NH, Bb), 128, FLASH_SMEM>>>();
    gemm_f16<false><<<dim3(8, 32), 256, GEMM_SMEM>>>(oh, woh, out, 1024, 1024);
}

// round 15
// speedup vs baseline: 1.0959x; 1.0935x over previous
#include <cuda_runtime.h>
#include <cuda_fp16.h>
#include <cstdint>
#include <math.h>

#define Bb 2
#define Ss 2048
#define Dd 1024
#define NH 16
#define NKV 4
#define HD 64
#define MM (Bb*Ss)

// ---------------- scratch (__device__ globals) ------------------------------
__device__ __align__(16) __half g_xh [MM * Dd];
__device__ __align__(16) __half g_wh [1536 * Dd];
__device__ __align__(16) __half g_woh[Dd * 1024];
__device__ __align__(16) __half g_qkvh[MM * 1536];
__device__ __align__(16) __half g_qh [Bb*NH *Ss*HD];
__device__ __align__(16) __half g_kh [Bb*NKV*Ss*HD];
__device__ __align__(16) __half g_vh [Bb*NKV*Ss*HD];
__device__ __align__(16) __half g_oh [MM * NH*HD];
__device__ __align__(16) float2 g_rope[Ss * 32];     // (cos, sin) table

// ---------------- warp-MMA helpers ------------------------------------------
__device__ __forceinline__ uint32_t smem_u32(const void* p) {
    uint32_t a;
    asm("{ .reg .u64 t; cvta.to.shared.u64 t, %1; cvt.u32.u64 %0, t; }" : "=r"(a) : "l"(p));
    return a;
}
__device__ __forceinline__ void mma16816(float* c, const uint32_t* a, uint32_t b0, uint32_t b1) {
    asm volatile("mma.sync.aligned.m16n8k16.row.col.f32.f16.f16.f32 "
                 "{%0,%1,%2,%3}, {%4,%5,%6,%7}, {%8,%9}, {%0,%1,%2,%3};"
                 : "+f"(c[0]), "+f"(c[1]), "+f"(c[2]), "+f"(c[3])
                 : "r"(a[0]), "r"(a[1]), "r"(a[2]), "r"(a[3]), "r"(b0), "r"(b1));
}
__device__ __forceinline__ void mma16816h(uint32_t* c, const uint32_t* a, uint32_t b0, uint32_t b1) {
    asm volatile("mma.sync.aligned.m16n8k16.row.col.f16.f16.f16.f16 "
                 "{%0,%1}, {%2,%3,%4,%5}, {%6,%7}, {%0,%1};"
                 : "+r"(c[0]), "+r"(c[1])
                 : "r"(a[0]), "r"(a[1]), "r"(a[2]), "r"(a[3]), "r"(b0), "r"(b1));
}
__device__ __forceinline__ void ldsm_x4(uint32_t* r, uint32_t a) {
    asm volatile("ldmatrix.sync.aligned.m8n8.x4.shared.b16 {%0,%1,%2,%3}, [%4];"
                 : "=r"(r[0]), "=r"(r[1]), "=r"(r[2]), "=r"(r[3]) : "r"(a));
}
__device__ __forceinline__ void ldsm_x4t(uint32_t* r, uint32_t a) {
    asm volatile("ldmatrix.sync.aligned.m8n8.x4.trans.shared.b16 {%0,%1,%2,%3}, [%4];"
                 : "=r"(r[0]), "=r"(r[1]), "=r"(r[2]), "=r"(r[3]) : "r"(a));
}
__device__ __forceinline__ uint32_t packh2(float x, float y) {
    __half2 h = __floats2half2_rn(x, y);
    return *reinterpret_cast<uint32_t*>(&h);
}
__device__ __forceinline__ void cp16(uint32_t dst, const void* src) {
    asm volatile("cp.async.cg.shared.global [%0], [%1], 16;" :: "r"(dst), "l"(src));
}
__device__ __forceinline__ __half2 u2h(uint32_t u) { return *reinterpret_cast<__half2*>(&u); }
__device__ __forceinline__ uint32_t h2u(__half2 h) { return *reinterpret_cast<uint32_t*>(&h); }
__device__ __forceinline__ float ex2a(float x) {
    float y;
    asm("ex2.approx.ftz.f32 %0, %1;" : "=f"(y) : "f"(x));
    return y;
}

// ---------------- fused fp32->fp16 conversions + rope table -----------------
__global__ void convall(const float* __restrict__ x,  const float* __restrict__ wq,
                        const float* __restrict__ wk, const float* __restrict__ wv,
                        const float* __restrict__ wo) {
    int i = blockIdx.x * blockDim.x + threadIdx.x;
    if (i >= 1703936) {
        if (i < 1703936 + Ss * 32) {
            int t = i - 1703936, s = t >> 5, j = t & 31;
            float ang = (float)s * expf(-(float)j * (9.210340371976184f / 32.f));
            float sn, cs; sincosf(ang, &sn, &cs);
            g_rope[t] = make_float2(cs, sn);
        }
        return;
    }
    const float4* s; __half2* d;
    if      (i < 1048576) {                      s = (const float4*)x  + i; d = (__half2*)g_xh            + 2 * i; }
    else if (i < 1310720) { int t = i - 1048576; s = (const float4*)wq + t; d = (__half2*)g_wh            + 2 * t; }
    else if (i < 1376256) { int t = i - 1310720; s = (const float4*)wk + t; d = (__half2*)(g_wh + 1048576) + 2 * t; }
    else if (i < 1441792) { int t = i - 1376256; s = (const float4*)wv + t; d = (__half2*)(g_wh + 1310720) + 2 * t; }
    else                  { int t = i - 1441792; s = (const float4*)wo + t; d = (__half2*)g_woh           + 2 * t; }
    float4 v = *s;
    d[0] = __floats2half2_rn(v.x, v.y);
    d[1] = __floats2half2_rn(v.z, v.w);
}

// ---------------- HMMA GEMM, 256 thr, warp 64x32, BK=64, cp.async 3-stage ---
#define AST 72
#define GEMM_SMEM 110592
template<bool HALF_OUT>
__global__ __launch_bounds__(256) void gemm_f16(const __half* __restrict__ A,
                                                const __half* __restrict__ B,
                                                void* __restrict__ Cv,
                                                int N, int K) {
    extern __shared__ __align__(16) char gsm[];
    const uint32_t gsb = smem_u32(gsm);
    const int tid = threadIdx.x, lane = tid & 31, wid = tid >> 5;
    const int wm = wid & 1, wn = wid >> 1;
    const int m0 = blockIdx.y * 128, n0 = blockIdx.x * 128;
    const int gid = lane >> 2, tig = lane & 3;
    const int rr = tid >> 3, cc8 = (tid & 7) * 8;

    float acc[4][4][4];
#pragma unroll
    for (int mi = 0; mi < 4; mi++)
#pragma unroll
        for (int ni = 0; ni < 4; ni++)
#pragma unroll
            for (int j = 0; j < 4; j++) acc[mi][ni][j] = 0.f;

    const int NKt = K >> 6;
#pragma unroll
    for (int st = 0; st < 2; st++) {
        if (st < NKt) {
            const int k0 = st << 6;
            uint32_t ab = gsb + st * 36864;
#pragma unroll
            for (int i = 0; i < 4; i++) {
                const int row = rr + i * 32;
                cp16(ab + ((row * AST + cc8) << 1),         A + (size_t)(m0 + row) * K + k0 + cc8);
                cp16(ab + 18432 + ((row * AST + cc8) << 1), B + (size_t)(n0 + row) * K + k0 + cc8);
            }
        }
        asm volatile("cp.async.commit_group;");
    }
    asm volatile("cp.async.wait_group 1;" ::: "memory");
    __syncthreads();

    int sc = 0, sp = 2;
    for (int kt = 0; kt < NKt; kt++) {
        if (kt + 2 < NKt) {
            const int k0 = (kt + 2) << 6;
            uint32_t ab = gsb + sp * 36864;
#pragma unroll
            for (int i = 0; i < 4; i++) {
                const int row = rr + i * 32;
                cp16(ab + ((row * AST + cc8) << 1),         A + (size_t)(m0 + row) * K + k0 + cc8);
                cp16(ab + 18432 + ((row * AST + cc8) << 1), B + (size_t)(n0 + row) * K + k0 + cc8);
            }
        }
        asm volatile("cp.async.commit_group;");

        const uint32_t asb = gsb + sc * 36864;
        const uint32_t bsb = asb + 18432;
#pragma unroll
        for (int ks = 0; ks < 4; ks++) {
            uint32_t af[4][4];
#pragma unroll
            for (int mi = 0; mi < 4; mi++)
                ldsm_x4(af[mi], asb + (((wm * 64 + mi * 16 + (lane & 15)) * AST
                                        + ks * 16 + (lane >> 4) * 8) << 1));
            uint32_t bfr[2][4];
#pragma unroll
            for (int ni2 = 0; ni2 < 2; ni2++)
                ldsm_x4(bfr[ni2], bsb + (((wn * 32 + ni2 * 16 + (lane & 15)) * AST
                                          + ks * 16 + (lane >> 4) * 8) << 1));
#pragma unroll
            for (int ni = 0; ni < 4; ni++) {
                const uint32_t b0 = bfr[ni >> 1][ni & 1], b1 = bfr[ni >> 1][(ni & 1) + 2];
#pragma unroll
                for (int mi = 0; mi < 4; mi++) mma16816(acc[mi][ni], af[mi], b0, b1);
            }
        }
        asm volatile("cp.async.wait_group 1;" ::: "memory");
        __syncthreads();
        sc = (sc == 2) ? 0 : sc + 1;
        sp = (sp == 2) ? 0 : sp + 1;
    }

#pragma unroll
    for (int mi = 0; mi < 4; mi++)
#pragma unroll
        for (int ni = 0; ni < 4; ni++) {
            const int row = m0 + wm * 64 + mi * 16 + gid;
            const int col = n0 + wn * 32 + ni * 8 + tig * 2;
            if (HALF_OUT) {
                __half* C = (__half*)Cv;
                *(__half2*)&C[(size_t)row * N + col]       = __floats2half2_rn(acc[mi][ni][0], acc[mi][ni][1]);
                *(__half2*)&C[(size_t)(row + 8) * N + col] = __floats2half2_rn(acc[mi][ni][2], acc[mi][ni][3]);
            } else {
                float* C = (float*)Cv;
                *(float2*)&C[(size_t)row * N + col]       = make_float2(acc[mi][ni][0], acc[mi][ni][1]);
                *(float2*)&C[(size_t)(row + 8) * N + col] = make_float2(acc[mi][ni][2], acc[mi][ni][3]);
            }
        }
}

// ---------------- fused RoPE + V layout (fp16 qkv input) ---------------------
#define QSCALE 0.1803368801111204f
__global__ void prep(const __half* __restrict__ qkv) {
    int idx = blockIdx.x * blockDim.x + threadIdx.x;
    if (idx < MM * NH * 32) {
        int j = idx & 31, hh = (idx >> 5) & 15, row = idx >> 9;
        int s = row & (Ss - 1), b = row >> 11;
        float2 r = g_rope[(s << 5) | j];
        const __half* p = qkv + (size_t)row * 1536 + hh * 64;
        float x1 = __half2float(p[j]), x2 = __half2float(p[j + 32]);
        __half* o = g_qh + ((size_t)(b * NH + hh) * Ss + s) * HD;
        o[j]      = __float2half((x1 * r.x - x2 * r.y) * QSCALE);
        o[j + 32] = __float2half((x2 * r.x + x1 * r.y) * QSCALE);
    } else if (idx < MM * NH * 32 + MM * NKV * 32) {
        int t = idx - MM * NH * 32;
        int j = t & 31, hh = (t >> 5) & 3, row = t >> 7;
        int s = row & (Ss - 1), b = row >> 11;
        float2 r = g_rope[(s << 5) | j];
        const __half* p = qkv + (size_t)row * 1536 + 1024 + hh * 64;
        float x1 = __half2float(p[j]), x2 = __half2float(p[j + 32]);
        __half* o = g_kh + ((size_t)(b * NKV + hh) * Ss + s) * HD;
        o[j]      = __float2half(x1 * r.x - x2 * r.y);
        o[j + 32] = __float2half(x2 * r.x + x1 * r.y);
    } else if (idx < MM * NH * 32 + MM * NKV * 32 + MM * NKV * 8) {
        int t = idx - (MM * NH * 32 + MM * NKV * 32);
        int d8 = t & 7, hh = (t >> 3) & 3, row = t >> 5;
        int s = row & (Ss - 1), b = row >> 11;
        uint4 v = *(const uint4*)(qkv + (size_t)row * 1536 + 1280 + hh * 64 + d8 * 8);
        *(uint4*)(g_vh + ((size_t)(b * NKV + hh) * Ss + s) * HD + d8 * 8) = v;
    }
}

// ---------------- flash attention: R12 config, LPT grid order ----------------
// grid(32 head-batch pairs, 32 qt). qt = 31 - blockIdx.y so ALL heavy CTAs
// have the lowest bids and start in wave 1 (LPT scheduling).
// smem: Q 9216 | K 2x9216 | V 2x9216 = 46080 -> 4 CTAs/SM.
#define FST 72
#define FLASH_SMEM 46080
__global__ __launch_bounds__(128) void flash_f16() {
    extern __shared__ __align__(16) char sm[];
    __half* Qs = (__half*)sm;
    const uint32_t qsb = smem_u32(sm);
    const uint32_t ksb0 = qsb + 9216, vsb0 = qsb + 27648;

    const int tid = threadIdx.x, lane = tid & 31, w = tid >> 5;
    const int pair = blockIdx.x;                     // 0..31
    const int qt = (gridDim.y - 1) - blockIdx.y;     // heavy (qt=31) at lowest bids
    const int h = pair & 15, b = pair >> 4;
    const int qm0 = qt * 64, kvh = h >> 2, qw0 = w * 16;
    const int gid = lane >> 2, tig = lane & 3;

    const __half* kb = g_kh + (size_t)(b * NKV + kvh) * Ss * HD;
    const __half* vb = g_vh + (size_t)(b * NKV + kvh) * Ss * HD;
    const int cr = tid >> 3, cc = (tid & 7) * 8;

    // prologue: tile 0 -> buf 0
#pragma unroll
    for (int i = 0; i < 4; i++) {
        cp16(ksb0 + (((cr + i * 16) * FST + cc) << 1), kb + (size_t)(cr + i * 16) * HD + cc);
        cp16(vsb0 + (((cr + i * 16) * FST + cc) << 1), vb + (size_t)(cr + i * 16) * HD + cc);
    }
    asm volatile("cp.async.commit_group;");

    const __half* qb = g_qh + ((size_t)(b * NH + h) * Ss + qm0) * HD;
#pragma unroll
    for (int i = 0; i < 4; i++) {
        int u = tid + i * 128, r = u >> 3, c = u & 7;
        *(uint4*)&Qs[r * FST + c * 8] = *(const uint4*)(qb + (size_t)r * HD + c * 8);
    }
    asm volatile("cp.async.wait_group 0;" ::: "memory");
    __syncthreads();

    uint32_t aQ[4][4];
#pragma unroll
    for (int ks = 0; ks < 4; ks++)
        ldsm_x4(aQ[ks], qsb + (((qw0 + (lane & 15)) * FST + ks * 16 + (lane >> 4) * 8) << 1));

    float oacc[8][4];
#pragma unroll
    for (int ni = 0; ni < 8; ni++)
#pragma unroll
        for (int j = 0; j < 4; j++) oacc[ni][j] = 0.f;
    float m0_ = -1e30f, m1_ = -1e30f, l0_ = 0.f, l1_ = 0.f;
    const int row0 = qm0 + qw0 + gid, row1 = row0 + 8;

    const int ntiles = qt + 1;
    int buf = 0;
    for (int t = 0; t < ntiles; t++) {
        const int n0 = t * 64;
        if (t + 1 < ntiles) {
            const int nn = n0 + 64;
            const uint32_t kd = ksb0 + (buf ^ 1) * 9216, vd = vsb0 + (buf ^ 1) * 9216;
#pragma unroll
            for (int i = 0; i < 4; i++) {
                cp16(kd + (((cr + i * 16) * FST + cc) << 1), kb + (size_t)(nn + cr + i * 16) * HD + cc);
                cp16(vd + (((cr + i * 16) * FST + cc) << 1), vb + (size_t)(nn + cr + i * 16) * HD + cc);
            }
        }
        asm volatile("cp.async.commit_group;");

        {
            const uint32_t ksb = ksb0 + buf * 9216, vsb = vsb0 + buf * 9216;

            uint32_t sh[8][2];
#pragma unroll
            for (int ni = 0; ni < 8; ni++) { sh[ni][0] = 0u; sh[ni][1] = 0u; }
#pragma unroll
            for (int ks = 0; ks < 4; ks++)
#pragma unroll
                for (int ni2 = 0; ni2 < 4; ni2++) {
                    uint32_t kr[4];
                    ldsm_x4(kr, ksb + (((ni2 * 16 + (lane & 15)) * FST + ks * 16 + (lane >> 4) * 8) << 1));
                    mma16816h(sh[ni2 * 2],     aQ[ks], kr[0], kr[2]);
                    mma16816h(sh[ni2 * 2 + 1], aQ[ks], kr[1], kr[3]);
                }

            float sacc[8][4];
#pragma unroll
            for (int ni = 0; ni < 8; ni++) {
                float2 lo = __half22float2(u2h(sh[ni][0]));
                float2 hi = __half22float2(u2h(sh[ni][1]));
                sacc[ni][0] = lo.x; sacc[ni][1] = lo.y; sacc[ni][2] = hi.x; sacc[ni][3] = hi.y;
            }
            if (n0 + 63 > row0) {
#pragma unroll
                for (int ni = 0; ni < 8; ni++) {
                    const int col = n0 + ni * 8 + tig * 2;
                    if (col     > row0) sacc[ni][0] = -1e30f;
                    if (col + 1 > row0) sacc[ni][1] = -1e30f;
                    if (col     > row1) sacc[ni][2] = -1e30f;
                    if (col + 1 > row1) sacc[ni][3] = -1e30f;
                }
            }

            float mx0 = -1e30f, mx1 = -1e30f;
#pragma unroll
            for (int ni = 0; ni < 8; ni++) {
                mx0 = fmaxf(mx0, fmaxf(sacc[ni][0], sacc[ni][1]));
                mx1 = fmaxf(mx1, fmaxf(sacc[ni][2], sacc[ni][3]));
            }
            __half2 mp = __floats2half2_rn(mx0, mx1);
            {
                uint32_t mu = h2u(mp);
                uint32_t o1 = __shfl_xor_sync(0xffffffffu, mu, 1);
                mp = __hmax2(mp, u2h(o1));
                mu = h2u(mp);
                uint32_t o2 = __shfl_xor_sync(0xffffffffu, mu, 2);
                mp = __hmax2(mp, u2h(o2));
            }
            float2 mf = __half22float2(mp);
            const float mn0 = fmaxf(m0_, mf.x), mn1 = fmaxf(m1_, mf.y);
            const float al0 = ex2a(m0_ - mn0), al1 = ex2a(m1_ - mn1);

            float s0 = 0.f, s1 = 0.f;
#pragma unroll
            for (int ni = 0; ni < 8; ni++) {
                sacc[ni][0] = ex2a(sacc[ni][0] - mn0);
                sacc[ni][1] = ex2a(sacc[ni][1] - mn0);
                sacc[ni][2] = ex2a(sacc[ni][2] - mn1);
                sacc[ni][3] = ex2a(sacc[ni][3] - mn1);
                s0 += sacc[ni][0] + sacc[ni][1];
                s1 += sacc[ni][2] + sacc[ni][3];
            }
            l0_ = l0_ * al0 + s0;
            l1_ = l1_ * al1 + s1;
            m0_ = mn0; m1_ = mn1;

            uint32_t aP[4][4];
#pragma unroll
            for (int ks = 0; ks < 4; ks++) {
                aP[ks][0] = packh2(sacc[2 * ks][0],     sacc[2 * ks][1]);
                aP[ks][1] = packh2(sacc[2 * ks][2],     sacc[2 * ks][3]);
                aP[ks][2] = packh2(sacc[2 * ks + 1][0], sacc[2 * ks + 1][1]);
                aP[ks][3] = packh2(sacc[2 * ks + 1][2], sacc[2 * ks + 1][3]);
            }
            if (!__all_sync(0xffffffffu, (al0 == 1.f) && (al1 == 1.f))) {
#pragma unroll
                for (int ni = 0; ni < 8; ni++) {
                    oacc[ni][0] *= al0; oacc[ni][1] *= al0;
                    oacc[ni][2] *= al1; oacc[ni][3] *= al1;
                }
            }
#pragma unroll
            for (int ks = 0; ks < 4; ks++)
#pragma unroll
                for (int ni2 = 0; ni2 < 4; ni2++) {
                    uint32_t vr[4];
                    ldsm_x4t(vr, vsb + (((ks * 16 + ((lane >> 3) & 1) * 8 + (lane & 7)) * FST
                                         + ni2 * 16 + (lane >> 4) * 8) << 1));
                    mma16816(oacc[ni2 * 2],     aP[ks], vr[0], vr[1]);
                    mma16816(oacc[ni2 * 2 + 1], aP[ks], vr[2], vr[3]);
                }
        }

        asm volatile("cp.async.wait_group 0;" ::: "memory");
        __syncthreads();
        buf ^= 1;
    }

    l0_ += __shfl_xor_sync(0xffffffffu, l0_, 1);
    l0_ += __shfl_xor_sync(0xffffffffu, l0_, 2);
    l1_ += __shfl_xor_sync(0xffffffffu, l1_, 1);
    l1_ += __shfl_xor_sync(0xffffffffu, l1_, 2);
    const float inv0 = 1.f / l0_, inv1 = 1.f / l1_;
    __half* ob = g_oh + (size_t)(b * Ss + qm0 + qw0) * (NH * HD) + h * HD;
#pragma unroll
    for (int ni = 0; ni < 8; ni++) {
        const int col = ni * 8 + tig * 2;
        __half2 o0 = __floats2half2_rn(oacc[ni][0] * inv0, oacc[ni][1] * inv0);
        __half2 o1 = __floats2half2_rn(oacc[ni][2] * inv1, oacc[ni][3] * inv1);
        *(__half2*)&ob[(size_t)gid * (NH * HD) + col]       = o0;
        *(__half2*)&ob[(size_t)(gid + 8) * (NH * HD) + col] = o1;
    }
}

// ---------------------------------------------------------------------------
extern "C" void kernel_launch(void* const* d_in, const int* in_sizes, int n_in,
                              void* d_out, int out_size) {
    const float* x  = (const float*)d_in[0];
    const float* Wq = (const float*)d_in[1];
    const float* Wk = (const float*)d_in[2];
    const float* Wv = (const float*)d_in[3];
    const float* Wo = (const float*)d_in[4];
    float* out = (float*)d_out;

    __half *xh, *wh, *woh, *oh, *qkvh;
    cudaGetSymbolAddress((void**)&xh,   g_xh);
    cudaGetSymbolAddress((void**)&wh,   g_wh);
    cudaGetSymbolAddress((void**)&woh,  g_woh);
    cudaGetSymbolAddress((void**)&oh,   g_oh);
    cudaGetSymbolAddress((void**)&qkvh, g_qkvh);

    cudaFuncSetAttribute(flash_f16, cudaFuncAttributeMaxDynamicSharedMemorySize, FLASH_SMEM);
    cudaFuncSetAttribute(gemm_f16<true>,  cudaFuncAttributeMaxDynamicSharedMemorySize, GEMM_SMEM);
    cudaFuncSetAttribute(gemm_f16<false>, cudaFuncAttributeMaxDynamicSharedMemorySize, GEMM_SMEM);

    convall<<<(1703936 + Ss * 32 + 255) / 256, 256>>>(x, Wq, Wk, Wv, Wo);
    gemm_f16<true><<<dim3(12, 32), 256, GEMM_SMEM>>>(xh, wh, qkvh, 1536, 1024);
    prep<<<(MM * NH * 32 + MM * NKV * 32 + MM * NKV * 8 + 255) / 256, 256>>>(qkvh);
    flash_f16<<<dim3(32, 32), 128, FLASH_SMEM>>>();
    gemm_f16<false><<<dim3(8, 32), 256, GEMM_SMEM>>>(oh, woh, out, 1024, 1024);
}